// round 1
// baseline (speedup 1.0000x reference)
#include <cuda_runtime.h>
#include <cuda_bf16.h>
#include <math.h>

// ---------------- problem constants ----------------
#define BATCH   4
#define SEQ     2048
#define HID     512
#define DFF     2048
#define NLAYER  4
#define NHEAD   4
#define DHEAD   128
#define WINDOW  606
#define KTRUE   30
#define NTOK    (BATCH*SEQ)          // 8192
#define LN_EPS  1e-5f

// ---------------- scratch (static device memory; no runtime alloc) ----------------
__device__ float g_x   [NTOK*HID];       // 16.8 MB
__device__ float g_qkv [NTOK*3*HID];     // 50 MB
__device__ float g_attn[NTOK*HID];       // 16.8 MB
__device__ float g_mid [NTOK*DFF];       // 67 MB
__device__ float g_t2  [NTOK*HID];       // 16.8 MB
__device__ float g_small[NTOK*16];
__device__ float g_yhat[NTOK*8];

// ---------------- helpers ----------------
__device__ __forceinline__ float gelu_exact(float v) {
    return 0.5f * v * (1.0f + erff(v * 0.7071067811865475f));
}

// ---------------- embed: u_aug @ W_in + b_in + pos_enc ----------------
// u: [B, 8, T], y: [B, 8, T], W_in: [24, 512]
__global__ void embed_kernel(const float* __restrict__ u, const float* __restrict__ y,
                             const float* __restrict__ W_in, const float* __restrict__ b_in,
                             float* __restrict__ x) {
    int n = blockIdx.x;            // token
    int c = threadIdx.x;           // channel 0..511
    int b = n >> 11;
    int t = n & (SEQ - 1);
    __shared__ float ua[24];
    if (c < 8)       ua[c] = u[(size_t)(b*8 + c)*SEQ + t];
    else if (c < 16) ua[c] = 0.0f;                                   // y_aug (phy) == 0
    else if (c < 24) ua[c] = (t < KTRUE) ? y[(size_t)(b*8 + (c-16))*SEQ + t] : 0.0f;
    __syncthreads();
    float s = b_in[c];
    #pragma unroll
    for (int k = 0; k < 24; k++) s = fmaf(ua[k], W_in[k*HID + c], s);
    // positional encoding
    int i2 = c & ~1;
    float div = __expf(-9.210340371976184f * (float)i2 / (float)HID);  // ln(10000)
    float ang = (float)t * div;
    s += (c & 1) ? cosf(ang) : sinf(ang);
    x[(size_t)n*HID + c] = s;
}

// ---------------- generic tiled fp32 GEMM: C = A[M,K] @ W[K,N] + bias, epilogue ----------------
// epi: 0 = bias only, 1 = bias + exact GELU
#define BM 64
#define BN 64
#define BKT 16
__global__ __launch_bounds__(256) void gemm_kernel(
    const float* __restrict__ A, const float* __restrict__ W,
    const float* __restrict__ bias, float* __restrict__ C,
    int M, int N, int K, int epi) {
    __shared__ float As[BKT][BM + 4];
    __shared__ float Bs[BKT][BN];
    const int bm = blockIdx.y * BM;
    const int bn = blockIdx.x * BN;
    const int tid = threadIdx.x;          // 256
    const int tx = tid & 15, ty = tid >> 4;
    const int ar = tid >> 2;              // 0..63 (A row within tile)
    const int ak = (tid & 3) * 4;         // 0,4,8,12 (A k within tile)
    const int bk = tid >> 4;              // 0..15 (B k within tile)
    const int bc = (tid & 15) * 4;        // 0..60 (B col within tile)
    const bool nfull = (bn + BN <= N);

    float acc[4][4];
    #pragma unroll
    for (int i = 0; i < 4; i++)
        #pragma unroll
        for (int j = 0; j < 4; j++) acc[i][j] = 0.0f;

    for (int kk = 0; kk < K; kk += BKT) {
        float4 av = *(const float4*)(A + (size_t)(bm + ar)*K + kk + ak);
        As[ak+0][ar] = av.x; As[ak+1][ar] = av.y; As[ak+2][ar] = av.z; As[ak+3][ar] = av.w;
        if (nfull) {
            float4 bv = *(const float4*)(W + (size_t)(kk + bk)*N + bn + bc);
            *(float4*)&Bs[bk][bc] = bv;
        } else {
            #pragma unroll
            for (int q = 0; q < 4; q++) {
                int cc = bn + bc + q;
                Bs[bk][bc+q] = (cc < N) ? W[(size_t)(kk + bk)*N + cc] : 0.0f;
            }
        }
        __syncthreads();
        #pragma unroll
        for (int k = 0; k < BKT; k++) {
            float a0 = As[k][ty*4+0], a1 = As[k][ty*4+1], a2 = As[k][ty*4+2], a3 = As[k][ty*4+3];
            float4 bv = *(float4*)&Bs[k][tx*4];
            acc[0][0] = fmaf(a0, bv.x, acc[0][0]); acc[0][1] = fmaf(a0, bv.y, acc[0][1]);
            acc[0][2] = fmaf(a0, bv.z, acc[0][2]); acc[0][3] = fmaf(a0, bv.w, acc[0][3]);
            acc[1][0] = fmaf(a1, bv.x, acc[1][0]); acc[1][1] = fmaf(a1, bv.y, acc[1][1]);
            acc[1][2] = fmaf(a1, bv.z, acc[1][2]); acc[1][3] = fmaf(a1, bv.w, acc[1][3]);
            acc[2][0] = fmaf(a2, bv.x, acc[2][0]); acc[2][1] = fmaf(a2, bv.y, acc[2][1]);
            acc[2][2] = fmaf(a2, bv.z, acc[2][2]); acc[2][3] = fmaf(a2, bv.w, acc[2][3]);
            acc[3][0] = fmaf(a3, bv.x, acc[3][0]); acc[3][1] = fmaf(a3, bv.y, acc[3][1]);
            acc[3][2] = fmaf(a3, bv.z, acc[3][2]); acc[3][3] = fmaf(a3, bv.w, acc[3][3]);
        }
        __syncthreads();
    }
    #pragma unroll
    for (int i = 0; i < 4; i++) {
        int row = bm + ty*4 + i;
        #pragma unroll
        for (int j = 0; j < 4; j++) {
            int col = bn + tx*4 + j;
            if (col < N) {
                float v = acc[i][j] + bias[col];
                if (epi == 1) v = gelu_exact(v);
                C[(size_t)row*N + col] = v;
            }
        }
    }
}

// ---------------- windowed causal attention (online softmax), 1 block per (token, head) ----------------
__global__ __launch_bounds__(128) void attn_kernel(const float* __restrict__ qkv,
                                                   float* __restrict__ out) {
    const int n  = blockIdx.x;            // token id (b*SEQ + t)
    const int hh = blockIdx.y;            // head
    const int t  = n & (SEQ - 1);
    const int tid = threadIdx.x;          // 128

    __shared__ float Ks[32][129];
    __shared__ float Vs[32][129];
    __shared__ float qs[DHEAD];
    __shared__ float sc[32];
    __shared__ float sh_scale, sh_m, sh_l;

    const float* qp = qkv + (size_t)n*(3*HID) + hh*DHEAD;
    qs[tid] = qp[tid];
    if (tid == 0) { sh_m = -1e30f; sh_l = 0.0f; }
    __syncthreads();

    float acc = 0.0f;
    int j0 = t - (WINDOW - 1); if (j0 < 0) j0 = 0;
    const float* kbase = qkv + (size_t)(n - t)*(3*HID);   // batch start

    for (int jc = j0; jc <= t; jc += 32) {
        int nk = t - jc + 1; if (nk > 32) nk = 32;
        // cooperative K/V load (coalesced 128-float rows)
        for (int e = tid; e < nk*DHEAD; e += 128) {
            int r = e >> 7, c = e & 127;
            const float* row = kbase + (size_t)(jc + r)*(3*HID) + hh*DHEAD;
            Ks[r][c] = row[HID + c];         // K slice
            Vs[r][c] = row[2*HID + c];       // V slice
        }
        __syncthreads();
        // scores: thread j handles key j (conflict-free via 129-pad)
        if (tid < nk) {
            float s = 0.0f;
            #pragma unroll 8
            for (int d = 0; d < DHEAD; d++) s = fmaf(qs[d], Ks[tid][d], s);
            sc[tid] = s * 0.08838834764831845f;   // 1/sqrt(128)
        }
        __syncthreads();
        // online softmax bookkeeping (serial over <=32 on thread 0)
        if (tid == 0) {
            float m = sh_m, mc = m;
            for (int j = 0; j < nk; j++) mc = fmaxf(mc, sc[j]);
            float lscale = __expf(m - mc);
            float lc = 0.0f;
            for (int j = 0; j < nk; j++) { float p = __expf(sc[j] - mc); sc[j] = p; lc += p; }
            sh_l = sh_l * lscale + lc;
            sh_m = mc;
            sh_scale = lscale;
        }
        __syncthreads();
        acc *= sh_scale;
        #pragma unroll 8
        for (int j = 0; j < nk; j++) acc = fmaf(sc[j], Vs[j][tid], acc);
        __syncthreads();
    }
    out[(size_t)n*HID + hh*DHEAD + tid] = acc / sh_l;
}

// ---------------- residual add + LayerNorm (in place on x) ----------------
__global__ __launch_bounds__(256) void ln_kernel(float* __restrict__ x,
                                                 const float* __restrict__ add,
                                                 const float* __restrict__ g,
                                                 const float* __restrict__ b) {
    const int n = blockIdx.x;
    const int tid = threadIdx.x;              // 256; each handles 2 channels
    const int c0 = tid, c1 = tid + 256;
    float v0 = x[(size_t)n*HID + c0];
    float v1 = x[(size_t)n*HID + c1];
    if (add) { v0 += add[(size_t)n*HID + c0]; v1 += add[(size_t)n*HID + c1]; }
    float s  = v0 + v1;
    float sq = v0*v0 + v1*v1;
    #pragma unroll
    for (int o = 16; o > 0; o >>= 1) {
        s  += __shfl_xor_sync(0xffffffffu, s,  o);
        sq += __shfl_xor_sync(0xffffffffu, sq, o);
    }
    __shared__ float ss[8], qq[8];
    __shared__ float sh_mean, sh_rstd;
    int w = tid >> 5;
    if ((tid & 31) == 0) { ss[w] = s; qq[w] = sq; }
    __syncthreads();
    if (tid == 0) {
        float S = 0.0f, Q = 0.0f;
        #pragma unroll
        for (int i = 0; i < 8; i++) { S += ss[i]; Q += qq[i]; }
        float mean = S * (1.0f/512.0f);
        float var  = Q * (1.0f/512.0f) - mean*mean;
        sh_mean = mean;
        sh_rstd = rsqrtf(var + LN_EPS);
    }
    __syncthreads();
    float mean = sh_mean, rstd = sh_rstd;
    x[(size_t)n*HID + c0] = (v0 - mean) * rstd * g[c0] + b[c0];
    x[(size_t)n*HID + c1] = (v1 - mean) * rstd * g[c1] + b[c1];
}

// ---------------- loss: sum((y_hat - y_t)^2), deterministic single block ----------------
__global__ __launch_bounds__(1024) void loss_kernel(const float* __restrict__ yhat,
                                                    const float* __restrict__ y,
                                                    float* __restrict__ out) {
    float s = 0.0f;
    for (int e = threadIdx.x; e < NTOK*8; e += 1024) {
        int n = e >> 3, d = e & 7;
        int b = n >> 11, t = n & (SEQ - 1);
        float diff = yhat[e] - y[(size_t)(b*8 + d)*SEQ + t];
        s = fmaf(diff, diff, s);
    }
    #pragma unroll
    for (int o = 16; o > 0; o >>= 1) s += __shfl_xor_sync(0xffffffffu, s, o);
    __shared__ float red[32];
    int w = threadIdx.x >> 5;
    if ((threadIdx.x & 31) == 0) red[w] = s;
    __syncthreads();
    if (threadIdx.x == 0) {
        float tot = 0.0f;
        #pragma unroll
        for (int i = 0; i < 32; i++) tot += red[i];
        out[0] = tot;
    }
}

// ---------------- host orchestration ----------------
static inline void run_gemm(const float* A, const float* W, const float* bias, float* C,
                            int M, int N, int K, int epi) {
    dim3 grid((N + BN - 1) / BN, M / BM);
    gemm_kernel<<<grid, 256>>>(A, W, bias, C, M, N, K, epi);
}

extern "C" void kernel_launch(void* const* d_in, const int* in_sizes, int n_in,
                              void* d_out, int out_size) {
    const float* u     = (const float*)d_in[0];
    const float* y     = (const float*)d_in[1];
    const float* W_in  = (const float*)d_in[2];
    const float* b_in  = (const float*)d_in[3];
    const float* qkv_w = (const float*)d_in[4];
    const float* qkv_b = (const float*)d_in[5];
    const float* out_w = (const float*)d_in[6];
    const float* out_b = (const float*)d_in[7];
    const float* ff1_w = (const float*)d_in[8];
    const float* ff1_b = (const float*)d_in[9];
    const float* ff2_w = (const float*)d_in[10];
    const float* ff2_b = (const float*)d_in[11];
    const float* ln1_g = (const float*)d_in[12];
    const float* ln1_b = (const float*)d_in[13];
    const float* ln2_g = (const float*)d_in[14];
    const float* ln2_b = (const float*)d_in[15];
    const float* lnf_g = (const float*)d_in[16];
    const float* lnf_b = (const float*)d_in[17];
    const float* xm1_w = (const float*)d_in[18];
    const float* xm1_b = (const float*)d_in[19];
    const float* xm2_w = (const float*)d_in[20];
    const float* xm2_b = (const float*)d_in[21];
    const float* me1_w = (const float*)d_in[22];
    const float* me1_b = (const float*)d_in[23];
    const float* me2_w = (const float*)d_in[24];
    const float* me2_b = (const float*)d_in[25];
    const float* me3_w = (const float*)d_in[26];
    const float* me3_b = (const float*)d_in[27];

    static float *px = nullptr, *pqkv, *pattn, *pmid, *pt2, *psmall, *pyhat;
    if (!px) {
        cudaGetSymbolAddress((void**)&px,    g_x);
        cudaGetSymbolAddress((void**)&pqkv,  g_qkv);
        cudaGetSymbolAddress((void**)&pattn, g_attn);
        cudaGetSymbolAddress((void**)&pmid,  g_mid);
        cudaGetSymbolAddress((void**)&pt2,   g_t2);
        cudaGetSymbolAddress((void**)&psmall,g_small);
        cudaGetSymbolAddress((void**)&pyhat, g_yhat);
    }

    // 1. embed + pos encoding
    embed_kernel<<<NTOK, HID>>>(u, y, W_in, b_in, px);

    // 2. transformer layers
    for (int l = 0; l < NLAYER; l++) {
        run_gemm(px, qkv_w + (size_t)l*HID*3*HID, qkv_b + (size_t)l*3*HID, pqkv,
                 NTOK, 3*HID, HID, 0);
        attn_kernel<<<dim3(NTOK, NHEAD), 128>>>(pqkv, pattn);
        run_gemm(pattn, out_w + (size_t)l*HID*HID, out_b + (size_t)l*HID, pt2,
                 NTOK, HID, HID, 0);
        ln_kernel<<<NTOK, 256>>>(px, pt2, ln1_g + l*HID, ln1_b + l*HID);
        run_gemm(px, ff1_w + (size_t)l*HID*DFF, ff1_b + (size_t)l*DFF, pmid,
                 NTOK, DFF, HID, 1);
        run_gemm(pmid, ff2_w + (size_t)l*DFF*HID, ff2_b + (size_t)l*HID, pt2,
                 NTOK, HID, DFF, 0);
        ln_kernel<<<NTOK, 256>>>(px, pt2, ln2_g + l*HID, ln2_b + l*HID);
    }

    // 3. final LN
    ln_kernel<<<NTOK, 256>>>(px, nullptr, lnf_g, lnf_b);

    // 4. head
    run_gemm(px,    xm1_w, xm1_b, pt2,    NTOK, HID, HID, 1);  // gelu(x@xm1)
    run_gemm(pt2,   xm2_w, xm2_b, psmall, NTOK, 16,  HID, 0);  // x_mean
    run_gemm(psmall,me1_w, me1_b, pt2,    NTOK, HID, 16,  1);  // gelu
    run_gemm(pt2,   me2_w, me2_b, pmid,   NTOK, HID, HID, 1);  // gelu
    run_gemm(pmid,  me3_w, me3_b, pyhat,  NTOK, 8,   HID, 0);  // y_hat

    // 5. loss
    loss_kernel<<<1, 1024>>>(pyhat, y, (float*)d_out);
}

// round 2
// speedup vs baseline: 3.1828x; 3.1828x over previous
#include <cuda_runtime.h>
#include <cuda_bf16.h>
#include <math.h>

// ---------------- problem constants ----------------
#define BATCH   4
#define SEQ     2048
#define HID     512
#define DFF     2048
#define NLAYER  4
#define NHEAD   4
#define DHEAD   128
#define WINDOW  606
#define KTRUE   30
#define NTOK    (BATCH*SEQ)          // 8192
#define LN_EPS  1e-5f

// ---------------- scratch (static device memory; no runtime alloc) ----------------
__device__ float g_x   [NTOK*HID];
__device__ float g_qkv [NTOK*3*HID];
__device__ float g_attn[NTOK*HID];
__device__ float g_mid [NTOK*DFF];
__device__ float g_t2  [NTOK*HID];
__device__ float g_small[NTOK*16];
__device__ float g_yhat[NTOK*8];

__device__ __forceinline__ float gelu_exact(float v) {
    return 0.5f * v * (1.0f + erff(v * 0.7071067811865475f));
}

// ---------------- embed: u_aug @ W_in + b_in + pos_enc ----------------
__global__ void embed_kernel(const float* __restrict__ u, const float* __restrict__ y,
                             const float* __restrict__ W_in, const float* __restrict__ b_in,
                             float* __restrict__ x) {
    int n = blockIdx.x;
    int c = threadIdx.x;
    int b = n >> 11;
    int t = n & (SEQ - 1);
    __shared__ float ua[24];
    if (c < 8)       ua[c] = u[(size_t)(b*8 + c)*SEQ + t];
    else if (c < 16) ua[c] = 0.0f;
    else if (c < 24) ua[c] = (t < KTRUE) ? y[(size_t)(b*8 + (c-16))*SEQ + t] : 0.0f;
    __syncthreads();
    float s = b_in[c];
    #pragma unroll
    for (int k = 0; k < 24; k++) s = fmaf(ua[k], W_in[k*HID + c], s);
    int i2 = c & ~1;
    float div = __expf(-9.210340371976184f * (float)i2 / (float)HID);
    float ang = (float)t * div;
    s += (c & 1) ? cosf(ang) : sinf(ang);
    x[(size_t)n*HID + c] = s;
}

// ---------------- big GEMM: 128x128 tile, 8x8 micro-tile ----------------
// Requires: M % 128 == 0, N % 128 == 0, K % 16 == 0
#define GBM 128
#define GBN 128
#define GBK 16
__global__ __launch_bounds__(256) void gemm128_kernel(
    const float* __restrict__ A, const float* __restrict__ W,
    const float* __restrict__ bias, float* __restrict__ C,
    int M, int N, int K, int epi) {
    __shared__ float As[GBK][GBM + 4];
    __shared__ float Bs[GBK][GBN + 4];
    const int bm = blockIdx.y * GBM;
    const int bn = blockIdx.x * GBN;
    const int tid = threadIdx.x;
    const int tx = tid & 15, ty = tid >> 4;
    const int arow = tid >> 1;
    const int ak = (tid & 1) * 4;
    const int br = tid >> 5;            // 0..7
    const int bc = (tid & 31) * 4;      // 0..124

    float acc[8][8];
    #pragma unroll
    for (int i = 0; i < 8; i++)
        #pragma unroll
        for (int j = 0; j < 8; j++) acc[i][j] = 0.0f;

    for (int kk = 0; kk < K; kk += GBK) {
        float4 a0 = *(const float4*)(A + (size_t)(bm + arow)*K + kk + ak);
        float4 a1 = *(const float4*)(A + (size_t)(bm + arow)*K + kk + ak + 8);
        As[ak+0][arow] = a0.x; As[ak+1][arow] = a0.y; As[ak+2][arow] = a0.z; As[ak+3][arow] = a0.w;
        As[ak+8][arow] = a1.x; As[ak+9][arow] = a1.y; As[ak+10][arow] = a1.z; As[ak+11][arow] = a1.w;
        *(float4*)&Bs[br][bc]     = *(const float4*)(W + (size_t)(kk + br)*N + bn + bc);
        *(float4*)&Bs[br + 8][bc] = *(const float4*)(W + (size_t)(kk + br + 8)*N + bn + bc);
        __syncthreads();
        #pragma unroll
        for (int k = 0; k < GBK; k++) {
            float4 av0 = *(float4*)&As[k][ty*4];
            float4 av1 = *(float4*)&As[k][ty*4 + 64];
            float4 bv0 = *(float4*)&Bs[k][tx*4];
            float4 bv1 = *(float4*)&Bs[k][tx*4 + 64];
            float a[8] = {av0.x, av0.y, av0.z, av0.w, av1.x, av1.y, av1.z, av1.w};
            float b[8] = {bv0.x, bv0.y, bv0.z, bv0.w, bv1.x, bv1.y, bv1.z, bv1.w};
            #pragma unroll
            for (int i = 0; i < 8; i++)
                #pragma unroll
                for (int j = 0; j < 8; j++)
                    acc[i][j] = fmaf(a[i], b[j], acc[i][j]);
        }
        __syncthreads();
    }
    #pragma unroll
    for (int i = 0; i < 8; i++) {
        int row = bm + ty*4 + ((i < 4) ? i : 60 + i);   // ty*4+i or ty*4+64+(i-4)
        #pragma unroll
        for (int jj = 0; jj < 2; jj++) {
            int col = bn + tx*4 + jj*64;
            float4 r;
            r.x = acc[i][jj*4+0] + bias[col+0];
            r.y = acc[i][jj*4+1] + bias[col+1];
            r.z = acc[i][jj*4+2] + bias[col+2];
            r.w = acc[i][jj*4+3] + bias[col+3];
            if (epi == 1) {
                r.x = gelu_exact(r.x); r.y = gelu_exact(r.y);
                r.z = gelu_exact(r.z); r.w = gelu_exact(r.w);
            }
            *(float4*)(C + (size_t)row*N + col) = r;
        }
    }
}

// ---------------- small GEMM (64x64 tile) for N=16 / N=8 heads ----------------
#define BM 64
#define BN 64
#define BKT 16
__global__ __launch_bounds__(256) void gemm_kernel(
    const float* __restrict__ A, const float* __restrict__ W,
    const float* __restrict__ bias, float* __restrict__ C,
    int M, int N, int K, int epi) {
    __shared__ float As[BKT][BM + 4];
    __shared__ float Bs[BKT][BN];
    const int bm = blockIdx.y * BM;
    const int bn = blockIdx.x * BN;
    const int tid = threadIdx.x;
    const int tx = tid & 15, ty = tid >> 4;
    const int ar = tid >> 2;
    const int ak = (tid & 3) * 4;
    const int bk = tid >> 4;
    const int bc = (tid & 15) * 4;
    const bool nfull = (bn + BN <= N);

    float acc[4][4];
    #pragma unroll
    for (int i = 0; i < 4; i++)
        #pragma unroll
        for (int j = 0; j < 4; j++) acc[i][j] = 0.0f;

    for (int kk = 0; kk < K; kk += BKT) {
        float4 av = *(const float4*)(A + (size_t)(bm + ar)*K + kk + ak);
        As[ak+0][ar] = av.x; As[ak+1][ar] = av.y; As[ak+2][ar] = av.z; As[ak+3][ar] = av.w;
        if (nfull) {
            *(float4*)&Bs[bk][bc] = *(const float4*)(W + (size_t)(kk + bk)*N + bn + bc);
        } else {
            #pragma unroll
            for (int q = 0; q < 4; q++) {
                int cc = bn + bc + q;
                Bs[bk][bc+q] = (cc < N) ? W[(size_t)(kk + bk)*N + cc] : 0.0f;
            }
        }
        __syncthreads();
        #pragma unroll
        for (int k = 0; k < BKT; k++) {
            float a0 = As[k][ty*4+0], a1 = As[k][ty*4+1], a2 = As[k][ty*4+2], a3 = As[k][ty*4+3];
            float4 bv = *(float4*)&Bs[k][tx*4];
            acc[0][0] = fmaf(a0, bv.x, acc[0][0]); acc[0][1] = fmaf(a0, bv.y, acc[0][1]);
            acc[0][2] = fmaf(a0, bv.z, acc[0][2]); acc[0][3] = fmaf(a0, bv.w, acc[0][3]);
            acc[1][0] = fmaf(a1, bv.x, acc[1][0]); acc[1][1] = fmaf(a1, bv.y, acc[1][1]);
            acc[1][2] = fmaf(a1, bv.z, acc[1][2]); acc[1][3] = fmaf(a1, bv.w, acc[1][3]);
            acc[2][0] = fmaf(a2, bv.x, acc[2][0]); acc[2][1] = fmaf(a2, bv.y, acc[2][1]);
            acc[2][2] = fmaf(a2, bv.z, acc[2][2]); acc[2][3] = fmaf(a2, bv.w, acc[2][3]);
            acc[3][0] = fmaf(a3, bv.x, acc[3][0]); acc[3][1] = fmaf(a3, bv.y, acc[3][1]);
            acc[3][2] = fmaf(a3, bv.z, acc[3][2]); acc[3][3] = fmaf(a3, bv.w, acc[3][3]);
        }
        __syncthreads();
    }
    #pragma unroll
    for (int i = 0; i < 4; i++) {
        int row = bm + ty*4 + i;
        #pragma unroll
        for (int j = 0; j < 4; j++) {
            int col = bn + tx*4 + j;
            if (col < N) {
                float v = acc[i][j] + bias[col];
                if (epi == 1) v = gelu_exact(v);
                C[(size_t)row*N + col] = v;
            }
        }
    }
}

// ---------------- flash attention: 64-query tile per block, online softmax ----------------
#define QT 64
#define KC 32
#define QPAD 132
#define KPAD 132
#define SPAD 33
// smem floats: Q 64*132=8448, K 32*132=4224, V 32*128=4096, S 64*33=2112, rm/rl/rs 64*3=192
#define FL_Q  0
#define FL_K  8448
#define FL_V  (8448+4224)
#define FL_S  (8448+4224+4096)
#define FL_RM (FL_S+2112)
#define FL_RL (FL_RM+64)
#define FL_RS (FL_RL+64)
#define FL_FLOATS (FL_RS+64)
#define FLASH_SMEM (FL_FLOATS*4)

__global__ __launch_bounds__(256) void flash_kernel(const float* __restrict__ qkv,
                                                    float* __restrict__ out) {
    extern __shared__ float sm[];
    float* Qs = sm + FL_Q;
    float* Ks = sm + FL_K;
    float* Vs = sm + FL_V;
    float* Ss = sm + FL_S;
    float* rm = sm + FL_RM;
    float* rl = sm + FL_RL;
    float* rs = sm + FL_RS;

    const int tid = threadIdx.x;
    const int n0 = blockIdx.x * QT;        // first token of tile
    const int hh = blockIdx.y;
    const int t0 = n0 & (SEQ - 1);
    const int bb = n0 >> 11;

    // load Q tile (coalesced)
    #pragma unroll
    for (int q = 0; q < 8; q++) {
        int idx = tid + q*256;
        int r = idx >> 5, c = (idx & 31) * 4;
        float4 v = *(const float4*)(qkv + (size_t)(n0 + r)*(3*HID) + hh*DHEAD + c);
        *(float4*)&Qs[r*QPAD + c] = v;
    }
    if (tid < QT) { rm[tid] = -1e30f; rl[tid] = 0.0f; }

    float acc[8][4];
    #pragma unroll
    for (int i = 0; i < 8; i++)
        #pragma unroll
        for (int j = 0; j < 4; j++) acc[i][j] = 0.0f;

    const int rgs = tid >> 4, cgs = tid & 15;   // score: rows rgs*4.., cols cgs*2..
    const int rg2 = tid >> 5, cg2 = tid & 31;   // PV: rows rg2*8.., cols cg2*4..
    int jstart = t0 - (WINDOW - 1); if (jstart < 0) jstart = 0;
    const int tmax = t0 + QT - 1;
    __syncthreads();

    for (int jc = jstart; jc <= tmax; jc += KC) {
        // load K/V chunk (clamped rows; invalid keys masked in score phase)
        #pragma unroll
        for (int q = 0; q < 4; q++) {
            int idx = tid + q*256;
            int r = idx >> 5, c = (idx & 31) * 4;
            int ja = jc + r; if (ja > tmax) ja = tmax;
            const float* base = qkv + (size_t)((bb << 11) + ja)*(3*HID) + hh*DHEAD + c;
            *(float4*)&Ks[r*KPAD + c] = *(const float4*)(base + HID);
            *(float4*)&Vs[r*DHEAD + c] = *(const float4*)(base + 2*HID);
        }
        __syncthreads();

        // scores: 4 rows x 2 cols per thread
        float s[4][2];
        #pragma unroll
        for (int i = 0; i < 4; i++) { s[i][0] = 0.0f; s[i][1] = 0.0f; }
        #pragma unroll 4
        for (int k = 0; k < DHEAD; k += 4) {
            float4 k0 = *(float4*)&Ks[(cgs*2+0)*KPAD + k];
            float4 k1 = *(float4*)&Ks[(cgs*2+1)*KPAD + k];
            #pragma unroll
            for (int i = 0; i < 4; i++) {
                float4 qv = *(float4*)&Qs[(rgs*4+i)*QPAD + k];
                s[i][0] = fmaf(qv.x, k0.x, s[i][0]); s[i][0] = fmaf(qv.y, k0.y, s[i][0]);
                s[i][0] = fmaf(qv.z, k0.z, s[i][0]); s[i][0] = fmaf(qv.w, k0.w, s[i][0]);
                s[i][1] = fmaf(qv.x, k1.x, s[i][1]); s[i][1] = fmaf(qv.y, k1.y, s[i][1]);
                s[i][1] = fmaf(qv.z, k1.z, s[i][1]); s[i][1] = fmaf(qv.w, k1.w, s[i][1]);
            }
        }
        #pragma unroll
        for (int i = 0; i < 4; i++) {
            int tr = t0 + rgs*4 + i;
            #pragma unroll
            for (int j = 0; j < 2; j++) {
                int ja = jc + cgs*2 + j;
                bool ok = (ja <= tr) && (ja > tr - WINDOW);
                Ss[(rgs*4+i)*SPAD + cgs*2 + j] = ok ? s[i][j]*0.08838834764831845f : -1e30f;
            }
        }
        __syncthreads();

        // per-row online softmax (64 threads, one row each)
        if (tid < QT) {
            float m = rm[tid];
            float mc = m;
            float* srow = &Ss[tid*SPAD];
            #pragma unroll
            for (int j = 0; j < KC; j++) mc = fmaxf(mc, srow[j]);
            float l = 0.0f;
            #pragma unroll
            for (int j = 0; j < KC; j++) {
                float sv = srow[j];
                float p = (sv <= -1e29f) ? 0.0f : __expf(sv - mc);
                srow[j] = p; l += p;
            }
            float sc = __expf(m - mc);   // 0 if m was -inf-ish and mc real; 1 if unchanged
            rl[tid] = rl[tid]*sc + l;
            rm[tid] = mc;
            rs[tid] = sc;
        }
        __syncthreads();

        // rescale accumulators + P@V (8 rows x 4 cols per thread)
        #pragma unroll
        for (int i = 0; i < 8; i++) {
            float sc = rs[rg2*8 + i];
            acc[i][0] *= sc; acc[i][1] *= sc; acc[i][2] *= sc; acc[i][3] *= sc;
        }
        #pragma unroll 8
        for (int j = 0; j < KC; j++) {
            float4 vv = *(float4*)&Vs[j*DHEAD + cg2*4];
            #pragma unroll
            for (int i = 0; i < 8; i++) {
                float p = Ss[(rg2*8+i)*SPAD + j];
                acc[i][0] = fmaf(p, vv.x, acc[i][0]);
                acc[i][1] = fmaf(p, vv.y, acc[i][1]);
                acc[i][2] = fmaf(p, vv.z, acc[i][2]);
                acc[i][3] = fmaf(p, vv.w, acc[i][3]);
            }
        }
        __syncthreads();
    }

    #pragma unroll
    for (int i = 0; i < 8; i++) {
        int r = rg2*8 + i;
        float inv = 1.0f / rl[r];
        float4 o;
        o.x = acc[i][0]*inv; o.y = acc[i][1]*inv; o.z = acc[i][2]*inv; o.w = acc[i][3]*inv;
        *(float4*)(out + (size_t)(n0 + r)*HID + hh*DHEAD + cg2*4) = o;
    }
}

// ---------------- residual add + LayerNorm ----------------
__global__ __launch_bounds__(256) void ln_kernel(float* __restrict__ x,
                                                 const float* __restrict__ add,
                                                 const float* __restrict__ g,
                                                 const float* __restrict__ b) {
    const int n = blockIdx.x;
    const int tid = threadIdx.x;
    const int c0 = tid, c1 = tid + 256;
    float v0 = x[(size_t)n*HID + c0];
    float v1 = x[(size_t)n*HID + c1];
    if (add) { v0 += add[(size_t)n*HID + c0]; v1 += add[(size_t)n*HID + c1]; }
    float s  = v0 + v1;
    float sq = v0*v0 + v1*v1;
    #pragma unroll
    for (int o = 16; o > 0; o >>= 1) {
        s  += __shfl_xor_sync(0xffffffffu, s,  o);
        sq += __shfl_xor_sync(0xffffffffu, sq, o);
    }
    __shared__ float ss[8], qq[8];
    __shared__ float sh_mean, sh_rstd;
    int w = tid >> 5;
    if ((tid & 31) == 0) { ss[w] = s; qq[w] = sq; }
    __syncthreads();
    if (tid == 0) {
        float S = 0.0f, Q = 0.0f;
        #pragma unroll
        for (int i = 0; i < 8; i++) { S += ss[i]; Q += qq[i]; }
        float mean = S * (1.0f/512.0f);
        float var  = Q * (1.0f/512.0f) - mean*mean;
        sh_mean = mean;
        sh_rstd = rsqrtf(var + LN_EPS);
    }
    __syncthreads();
    float mean = sh_mean, rstd = sh_rstd;
    x[(size_t)n*HID + c0] = (v0 - mean) * rstd * g[c0] + b[c0];
    x[(size_t)n*HID + c1] = (v1 - mean) * rstd * g[c1] + b[c1];
}

// ---------------- loss ----------------
__global__ __launch_bounds__(1024) void loss_kernel(const float* __restrict__ yhat,
                                                    const float* __restrict__ y,
                                                    float* __restrict__ out) {
    float s = 0.0f;
    for (int e = threadIdx.x; e < NTOK*8; e += 1024) {
        int n = e >> 3, d = e & 7;
        int b = n >> 11, t = n & (SEQ - 1);
        float diff = yhat[e] - y[(size_t)(b*8 + d)*SEQ + t];
        s = fmaf(diff, diff, s);
    }
    #pragma unroll
    for (int o = 16; o > 0; o >>= 1) s += __shfl_xor_sync(0xffffffffu, s, o);
    __shared__ float red[32];
    int w = threadIdx.x >> 5;
    if ((threadIdx.x & 31) == 0) red[w] = s;
    __syncthreads();
    if (threadIdx.x == 0) {
        float tot = 0.0f;
        #pragma unroll
        for (int i = 0; i < 32; i++) tot += red[i];
        out[0] = tot;
    }
}

// ---------------- host orchestration ----------------
static inline void run_gemm128(const float* A, const float* W, const float* bias, float* C,
                               int M, int N, int K, int epi) {
    dim3 grid(N / GBN, M / GBM);
    gemm128_kernel<<<grid, 256>>>(A, W, bias, C, M, N, K, epi);
}
static inline void run_gemm_small(const float* A, const float* W, const float* bias, float* C,
                                  int M, int N, int K, int epi) {
    dim3 grid((N + BN - 1) / BN, M / BM);
    gemm_kernel<<<grid, 256>>>(A, W, bias, C, M, N, K, epi);
}

extern "C" void kernel_launch(void* const* d_in, const int* in_sizes, int n_in,
                              void* d_out, int out_size) {
    const float* u     = (const float*)d_in[0];
    const float* y     = (const float*)d_in[1];
    const float* W_in  = (const float*)d_in[2];
    const float* b_in  = (const float*)d_in[3];
    const float* qkv_w = (const float*)d_in[4];
    const float* qkv_b = (const float*)d_in[5];
    const float* out_w = (const float*)d_in[6];
    const float* out_b = (const float*)d_in[7];
    const float* ff1_w = (const float*)d_in[8];
    const float* ff1_b = (const float*)d_in[9];
    const float* ff2_w = (const float*)d_in[10];
    const float* ff2_b = (const float*)d_in[11];
    const float* ln1_g = (const float*)d_in[12];
    const float* ln1_b = (const float*)d_in[13];
    const float* ln2_g = (const float*)d_in[14];
    const float* ln2_b = (const float*)d_in[15];
    const float* lnf_g = (const float*)d_in[16];
    const float* lnf_b = (const float*)d_in[17];
    const float* xm1_w = (const float*)d_in[18];
    const float* xm1_b = (const float*)d_in[19];
    const float* xm2_w = (const float*)d_in[20];
    const float* xm2_b = (const float*)d_in[21];
    const float* me1_w = (const float*)d_in[22];
    const float* me1_b = (const float*)d_in[23];
    const float* me2_w = (const float*)d_in[24];
    const float* me2_b = (const float*)d_in[25];
    const float* me3_w = (const float*)d_in[26];
    const float* me3_b = (const float*)d_in[27];

    static float *px = nullptr, *pqkv, *pattn, *pmid, *pt2, *psmall, *pyhat;
    static bool attr_set = false;
    if (!px) {
        cudaGetSymbolAddress((void**)&px,    g_x);
        cudaGetSymbolAddress((void**)&pqkv,  g_qkv);
        cudaGetSymbolAddress((void**)&pattn, g_attn);
        cudaGetSymbolAddress((void**)&pmid,  g_mid);
        cudaGetSymbolAddress((void**)&pt2,   g_t2);
        cudaGetSymbolAddress((void**)&psmall,g_small);
        cudaGetSymbolAddress((void**)&pyhat, g_yhat);
    }
    if (!attr_set) {
        cudaFuncSetAttribute(flash_kernel, cudaFuncAttributeMaxDynamicSharedMemorySize, FLASH_SMEM);
        attr_set = true;
    }

    embed_kernel<<<NTOK, HID>>>(u, y, W_in, b_in, px);

    for (int l = 0; l < NLAYER; l++) {
        run_gemm128(px, qkv_w + (size_t)l*HID*3*HID, qkv_b + (size_t)l*3*HID, pqkv,
                    NTOK, 3*HID, HID, 0);
        flash_kernel<<<dim3(NTOK/QT, NHEAD), 256, FLASH_SMEM>>>(pqkv, pattn);
        run_gemm128(pattn, out_w + (size_t)l*HID*HID, out_b + (size_t)l*HID, pt2,
                    NTOK, HID, HID, 0);
        ln_kernel<<<NTOK, 256>>>(px, pt2, ln1_g + l*HID, ln1_b + l*HID);
        run_gemm128(px, ff1_w + (size_t)l*HID*DFF, ff1_b + (size_t)l*DFF, pmid,
                    NTOK, DFF, HID, 1);
        run_gemm128(pmid, ff2_w + (size_t)l*DFF*HID, ff2_b + (size_t)l*HID, pt2,
                    NTOK, HID, DFF, 0);
        ln_kernel<<<NTOK, 256>>>(px, pt2, ln2_g + l*HID, ln2_b + l*HID);
    }

    ln_kernel<<<NTOK, 256>>>(px, nullptr, lnf_g, lnf_b);

    run_gemm128(px,    xm1_w, xm1_b, pt2,    NTOK, HID, HID, 1);
    run_gemm_small(pt2, xm2_w, xm2_b, psmall, NTOK, 16,  HID, 0);
    run_gemm128(psmall, me1_w, me1_b, pt2,   NTOK, HID, 16,  1);
    run_gemm128(pt2,   me2_w, me2_b, pmid,   NTOK, HID, HID, 1);
    run_gemm_small(pmid, me3_w, me3_b, pyhat, NTOK, 8,  HID, 0);

    loss_kernel<<<1, 1024>>>(pyhat, y, (float*)d_out);
}